// round 3
// baseline (speedup 1.0000x reference)
#include <cuda_runtime.h>

#define BB   16
#define NN   4096
#define CC   64
#define KNNK 32
#define TILE 2048
#define QB   128

#define F_INF __int_as_float(0x7f800000)
#define FULL  0xFFFFFFFFu

// Scratch (static device globals — allowed; no runtime allocation).
__device__ int   g_idx[BB * NN * KNNK];      // 8 MB
__device__ float g_mx[BB * NN * CC];         // 16 MB
__device__ float g_mn[BB * NN * CC];         // 16 MB
__device__ float g_part[BB * NN / 8];        // 8192 block partials
__device__ float g_inv;

// Branchless insert of c into ascending sorted 32-reg array (drops old max).
__device__ __forceinline__ void insert32(float (&sv)[KNNK], float c) {
#pragma unroll
    for (int u = 0; u < KNNK; u++) {
        float lo = fminf(sv[u], c);
        c = fmaxf(sv[u], c);
        sv[u] = lo;
    }
}

// ---------------------------------------------------------------------------
// Kernel 1: exact 32-NN per point, two-phase register-only selection.
// Phase 1: exact 32nd-smallest distance per query (values only, FMNMX chains,
//          buffered accepts, votes amortized over 2-candidate groups).
// Phase 2: rescan, emit index set (asc. index order, jax-compatible ties).
// ---------------------------------------------------------------------------
__global__ void __launch_bounds__(QB) knn_kernel(const float* __restrict__ xyz) {
    __shared__ float4 tile[TILE];                    // 32 KB

    const int b = blockIdx.x >> 5;                   // 32 blocks per batch
    const int i = ((blockIdx.x & 31) << 7) + threadIdx.x;
    const float* xb = xyz + (size_t)b * (3 * NN);

    const float xi = xb[i], yi = xb[NN + i], zi = xb[2 * NN + i];
    const float ax = -2.f * xi, ay = -2.f * yi, az = -2.f * zi;

    float sv[KNNK];
#pragma unroll
    for (int u = 0; u < KNNK; u++) sv[u] = F_INF;
    float worst = F_INF;
    float b0 = F_INF, b1 = F_INF, b2 = F_INF, b3 = F_INF;
    int cnt = 0;

    // ---------------- Phase 1: exact 32 smallest distance VALUES ----------
    for (int t0 = 0; t0 < NN; t0 += TILE) {
        __syncthreads();
        for (int t = threadIdx.x; t < TILE; t += QB) {
            float X = xb[t0 + t], Y = xb[NN + t0 + t], Z = xb[2 * NN + t0 + t];
            tile[t] = make_float4(X, Y, Z, fmaf(X, X, fmaf(Y, Y, Z * Z)));
        }
        __syncthreads();

#pragma unroll 4
        for (int jj = 0; jj < TILE; jj += 2) {
            float4 q0 = tile[jj];
            float4 q1 = tile[jj + 1];
            // d_rel = ||xj||^2 - 2 xi.xj  (ranking-equivalent to reference pd)
            float d0 = fmaf(ax, q0.x, fmaf(ay, q0.y, fmaf(az, q0.z, q0.w)));
            float d1 = fmaf(ax, q1.x, fmaf(ay, q1.y, fmaf(az, q1.z, q1.w)));
            bool p0 = d0 < worst;
            bool p1 = d1 < worst;
            if (__any_sync(FULL, p0 | p1)) {
                if (p0) { b3 = b2; b2 = b1; b1 = b0; b0 = d0; cnt++; }
                if (p1) { b3 = b2; b2 = b1; b1 = b0; b0 = d1; cnt++; }
                if (__any_sync(FULL, cnt >= 3)) {
                    insert32(sv, b0); insert32(sv, b1);
                    insert32(sv, b2); insert32(sv, b3);
                    b0 = b1 = b2 = b3 = F_INF; cnt = 0;
                    worst = sv[KNNK - 1];
                }
            }
        }
    }
    // final flush (sentinels are harmless)
    insert32(sv, b0); insert32(sv, b1); insert32(sv, b2); insert32(sv, b3);

    const float w = sv[KNNK - 1];                    // exact 32nd smallest
    int ties = 1;                                    // allowed emissions == w
#pragma unroll
    for (int u = 0; u < KNNK - 1; u++) ties += (sv[u] == w);

    // ---------------- Phase 2: recover the index set ----------------------
    const int base = (b * NN + i) * KNNK;
    int cnt2 = 0;
    for (int t0 = 0; t0 < NN; t0 += TILE) {
        __syncthreads();
        for (int t = threadIdx.x; t < TILE; t += QB) {
            float X = xb[t0 + t], Y = xb[NN + t0 + t], Z = xb[2 * NN + t0 + t];
            tile[t] = make_float4(X, Y, Z, fmaf(X, X, fmaf(Y, Y, Z * Z)));
        }
        __syncthreads();

#pragma unroll 4
        for (int jj = 0; jj < TILE; jj += 2) {
            float4 q0 = tile[jj];
            float4 q1 = tile[jj + 1];
            float d0 = fmaf(ax, q0.x, fmaf(ay, q0.y, fmaf(az, q0.z, q0.w)));
            float d1 = fmaf(ax, q1.x, fmaf(ay, q1.y, fmaf(az, q1.z, q1.w)));
            bool lt0 = d0 < w, eq0 = (d0 == w);
            bool lt1 = d1 < w, eq1 = (d1 == w);
            if (__any_sync(FULL, lt0 | eq0 | lt1 | eq1)) {
                if (lt0 | (eq0 & (ties > 0))) {
                    g_idx[base + cnt2] = t0 + jj;
                    cnt2++;
                    ties -= eq0 ? 1 : 0;
                }
                if (lt1 | (eq1 & (ties > 0))) {
                    g_idx[base + cnt2] = t0 + jj + 1;
                    cnt2++;
                    ties -= eq1 ? 1 : 0;
                }
            }
        }
    }
}

// ---------------------------------------------------------------------------
// Kernel 2: warp per (b,i). Lane = channel pair. Coalesced 256B row gathers.
// Produces per-channel max/min of offsets + block partial of sum(offset^2).
// ---------------------------------------------------------------------------
__global__ void __launch_bounds__(256) gather_kernel(const float* __restrict__ feats) {
    const int gw   = (blockIdx.x << 3) + (threadIdx.x >> 5);   // b*NN + i
    const int lane = threadIdx.x & 31;
    const int b = gw >> 12;
    const int i = gw & (NN - 1);
    const float* fb = feats + ((size_t)b << 18);               // b*NN*CC

    const float2 ctr = *(const float2*)(fb + i * CC + lane * 2);
    const int myid = g_idx[gw * KNNK + lane];

    float mx0 = __int_as_float(0xFF800000), mx1 = mx0;
    float mn0 = F_INF, mn1 = F_INF;
    float ss = 0.f;

#pragma unroll
    for (int k = 0; k < KNNK; k++) {
        int j = __shfl_sync(FULL, myid, k);
        float2 f = *(const float2*)(fb + j * CC + lane * 2);
        float o0 = f.x - ctr.x, o1 = f.y - ctr.y;
        mx0 = fmaxf(mx0, o0); mn0 = fminf(mn0, o0);
        mx1 = fmaxf(mx1, o1); mn1 = fminf(mn1, o1);
        ss = fmaf(o0, o0, ss);
        ss = fmaf(o1, o1, ss);
    }

    const int ob = gw * CC + lane * 2;
    *(float2*)(g_mx + ob) = make_float2(mx0, mx1);
    *(float2*)(g_mn + ob) = make_float2(mn0, mn1);

#pragma unroll
    for (int off = 16; off; off >>= 1)
        ss += __shfl_xor_sync(FULL, ss, off);

    __shared__ float bs[8];
    if (lane == 0) bs[threadIdx.x >> 5] = ss;
    __syncthreads();
    if (threadIdx.x == 0) {
        g_part[blockIdx.x] = bs[0] + bs[1] + bs[2] + bs[3] +
                             bs[4] + bs[5] + bs[6] + bs[7];
    }
}

// ---------------------------------------------------------------------------
// Kernel 3: reduce partials -> g_inv = 1/(sigma + eps)
// ---------------------------------------------------------------------------
__global__ void reduce_kernel() {
    __shared__ float sm[256];
    float s = 0.f;
    for (int t = threadIdx.x; t < BB * NN / 8; t += 256) s += g_part[t];
    sm[threadIdx.x] = s;
    __syncthreads();
#pragma unroll
    for (int o = 128; o; o >>= 1) {
        if (threadIdx.x < o) sm[threadIdx.x] += sm[threadIdx.x + o];
        __syncthreads();
    }
    if (threadIdx.x == 0) {
        float sigma = sm[0] / (float)((long long)BB * NN * KNNK * CC);
        g_inv = 1.f / (sigma + 1e-5f);
    }
}

// ---------------------------------------------------------------------------
// Kernel 4: pooled = select(alpha>=0, max, min) * inv * alpha + beta
// (max over k commutes with the positive/negative scale)
// ---------------------------------------------------------------------------
__global__ void __launch_bounds__(256) final_kernel(const float* __restrict__ alpha,
                                                    const float* __restrict__ beta,
                                                    float* __restrict__ out) {
    const int idx = blockIdx.x * 256 + threadIdx.x;   // float2 index, 2M total
    const float inv = g_inv;
    const int c2 = idx & (CC / 2 - 1);
    const float a0 = alpha[c2 * 2], a1 = alpha[c2 * 2 + 1];
    const float b0 = beta[c2 * 2],  b1 = beta[c2 * 2 + 1];
    const float2 mx = ((const float2*)g_mx)[idx];
    const float2 mn = ((const float2*)g_mn)[idx];
    float v0 = (a0 >= 0.f) ? mx.x : mn.x;
    float v1 = (a1 >= 0.f) ? mx.y : mn.y;
    float2 r;
    r.x = fmaf(v0 * inv, a0, b0);
    r.y = fmaf(v1 * inv, a1, b1);
    ((float2*)out)[idx] = r;
}

extern "C" void kernel_launch(void* const* d_in, const int* in_sizes, int n_in,
                              void* d_out, int out_size) {
    const float* xyz   = (const float*)d_in[0];
    const float* feats = (const float*)d_in[1];
    const float* alpha = (const float*)d_in[2];
    const float* beta  = (const float*)d_in[3];
    float* out = (float*)d_out;
    (void)in_sizes; (void)n_in; (void)out_size;

    knn_kernel<<<BB * NN / QB, QB>>>(xyz);
    gather_kernel<<<BB * NN / 8, 256>>>(feats);
    reduce_kernel<<<1, 256>>>();
    final_kernel<<<BB * NN * CC / 512, 256>>>(alpha, beta, out);
}

// round 5
// speedup vs baseline: 1.1052x; 1.1052x over previous
#include <cuda_runtime.h>

#define BB   16
#define NN   4096
#define CC   64
#define KNNK 32
#define TILE 2048
#define NPAIR (TILE / 2)
#define QB   128
#define CAP  320

#define F_INF  __int_as_float(0x7f800000)
#define F_NINF __int_as_float(0xff800000)
#define FULL   0xFFFFFFFFu

typedef unsigned long long ull;

// Scratch (static device globals — allowed; no runtime allocation).
__device__ int   g_idx[BB * NN * KNNK];      // 8 MB
__device__ float g_mx[BB * NN * CC];         // 16 MB
__device__ float g_mn[BB * NN * CC];         // 16 MB
__device__ float g_part[BB * NN / 8];        // 8192 block partials
__device__ float g_inv;

// ---- Blackwell packed f32x2 FMA (PTX-only; min/max.f32x2 do NOT exist) ----
__device__ __forceinline__ ull fma2(ull a, ull b, ull c) {
    ull d; asm("fma.rn.f32x2 %0, %1, %2, %3;" : "=l"(d) : "l"(a), "l"(b), "l"(c));
    return d;
}
__device__ __forceinline__ ull pk2(float lo, float hi) {
    ull r; asm("mov.b64 %0, {%1, %2};" : "=l"(r) : "f"(lo), "f"(hi));
    return r;
}
__device__ __forceinline__ void up2(ull v, float& lo, float& hi) {
    asm("mov.b64 {%0, %1}, %2;" : "=f"(lo), "=f"(hi) : "l"(v));
}

// Branchless insert of c into ascending sorted 32-reg array (drops old max).
__device__ __forceinline__ void insert32(float (&sv)[KNNK], float c) {
#pragma unroll
    for (int u = 0; u < KNNK; u++) {
        float lo = fminf(sv[u], c);
        c = fmaxf(sv[u], c);
        sv[u] = lo;
    }
}

// ---------------------------------------------------------------------------
// Kernel 1: exact 32-NN. Single sweep with packed FFMA2 distances; accepted
// candidates recorded (in ascending-index order) to a local-memory list that
// is replayed to emit the final index set. Block-uniform exact-rescan
// fallback on (astronomically unlikely) record overflow.
// ---------------------------------------------------------------------------
__global__ void __launch_bounds__(QB) knn_kernel(const float* __restrict__ xyz) {
    // pair-SoA tiles: tA[p]=(x0,x1,y0,y1), tB[p]=(z0,z1,n0,n1) for cands 2p,2p+1
    __shared__ float4 tA[NPAIR], tB[NPAIR];          // 32 KB
    __shared__ int s_of;

    const int b = blockIdx.x >> 5;                   // 32 blocks per batch
    const int i = ((blockIdx.x & 31) << 7) + threadIdx.x;
    const float* xb = xyz + (size_t)b * (3 * NN);

    if (threadIdx.x == 0) s_of = 0;

    const float xi = xb[i], yi = xb[NN + i], zi = xb[2 * NN + i];
    const ull AX = pk2(-2.f * xi, -2.f * xi);
    const ull AY = pk2(-2.f * yi, -2.f * yi);
    const ull AZ = pk2(-2.f * zi, -2.f * zi);

    float sv[KNNK];
#pragma unroll
    for (int u = 0; u < KNNK; u++) sv[u] = F_INF;
    float worst = F_INF;
    float b0 = F_INF, b1 = F_INF, b2 = F_INF, b3 = F_INF;
    int cnt = 0;

    float2 rec[CAP];                                 // local mem (d, idx-bits)
    int rc = 0;
    bool ofl = false;

    // ---------------- Phase 1: values + accepted-candidate record ---------
    for (int t0 = 0; t0 < NN; t0 += TILE) {
        __syncthreads();
        for (int p = threadIdx.x; p < NPAIR; p += QB) {
            float2 X = *(const float2*)(xb + t0 + 2 * p);
            float2 Y = *(const float2*)(xb + NN + t0 + 2 * p);
            float2 Z = *(const float2*)(xb + 2 * NN + t0 + 2 * p);
            float n0 = fmaf(X.x, X.x, fmaf(Y.x, Y.x, Z.x * Z.x));
            float n1 = fmaf(X.y, X.y, fmaf(Y.y, Y.y, Z.y * Z.y));
            tA[p] = make_float4(X.x, X.y, Y.x, Y.y);
            tB[p] = make_float4(Z.x, Z.y, n0, n1);
        }
        __syncthreads();

#pragma unroll 4
        for (int p = 0; p < NPAIR; p++) {
            float4 qa = tA[p];
            float4 qb = tB[p];
            // d_rel = ||xj||^2 - 2 xi.xj  (ranking-equivalent to reference pd)
            ull d2 = fma2(AX, pk2(qa.x, qa.y),
                     fma2(AY, pk2(qa.z, qa.w),
                     fma2(AZ, pk2(qb.x, qb.y), pk2(qb.z, qb.w))));
            float d0, d1; up2(d2, d0, d1);
            bool p0 = d0 < worst;
            bool p1 = d1 < worst;
            if (__any_sync(FULL, p0 | p1)) {
                if (p0) {
                    b3 = b2; b2 = b1; b1 = b0; b0 = d0; cnt++;
                    if (rc < CAP) rec[rc++] = make_float2(d0, __int_as_float(t0 + 2 * p));
                    else ofl = true;
                }
                if (p1) {
                    b3 = b2; b2 = b1; b1 = b0; b0 = d1; cnt++;
                    if (rc < CAP) rec[rc++] = make_float2(d1, __int_as_float(t0 + 2 * p + 1));
                    else ofl = true;
                }
                if (__any_sync(FULL, cnt >= 3)) {
                    insert32(sv, b0); insert32(sv, b1);
                    insert32(sv, b2); insert32(sv, b3);
                    b0 = b1 = b2 = b3 = F_INF; cnt = 0;
                    worst = sv[KNNK - 1];
                }
            }
        }
    }
    // final flush (sentinels are harmless)
    insert32(sv, b0); insert32(sv, b1); insert32(sv, b2); insert32(sv, b3);

    const float w = sv[KNNK - 1];                    // exact 32nd smallest
    int ties = 1;                                    // emissions allowed at ==w
#pragma unroll
    for (int u = 0; u < KNNK - 1; u++) ties += (sv[u] == w);

    if (ofl) atomicOr(&s_of, 1);
    __syncthreads();
    const bool any_of = (s_of != 0);

    // ---------------- Phase 2a: replay recorded list (fast path) ----------
    const int base = (b * NN + i) * KNNK;
    if (!ofl) {
        int cnt2 = 0;
        for (int t = 0; t < rc; t++) {
            float2 r = rec[t];
            float d = r.x;
            bool lt = d < w;
            bool eq = (d == w);
            if (lt | (eq & (ties > 0))) {
                g_idx[base + cnt2] = __float_as_int(r.y);
                cnt2++;
                ties -= eq ? 1 : 0;
            }
        }
    }

    // ---------------- Phase 2b: exact rescan fallback (block-uniform) -----
    if (any_of) {
        int cnt2 = 0;
        for (int t0 = 0; t0 < NN; t0 += TILE) {
            __syncthreads();
            for (int p = threadIdx.x; p < NPAIR; p += QB) {
                float2 X = *(const float2*)(xb + t0 + 2 * p);
                float2 Y = *(const float2*)(xb + NN + t0 + 2 * p);
                float2 Z = *(const float2*)(xb + 2 * NN + t0 + 2 * p);
                float n0 = fmaf(X.x, X.x, fmaf(Y.x, Y.x, Z.x * Z.x));
                float n1 = fmaf(X.y, X.y, fmaf(Y.y, Y.y, Z.y * Z.y));
                tA[p] = make_float4(X.x, X.y, Y.x, Y.y);
                tB[p] = make_float4(Z.x, Z.y, n0, n1);
            }
            __syncthreads();

            if (ofl) {
                for (int p = 0; p < NPAIR; p++) {
                    float4 qa = tA[p];
                    float4 qb = tB[p];
                    ull d2 = fma2(AX, pk2(qa.x, qa.y),
                             fma2(AY, pk2(qa.z, qa.w),
                             fma2(AZ, pk2(qb.x, qb.y), pk2(qb.z, qb.w))));
                    float d0, d1; up2(d2, d0, d1);
                    bool lt0 = d0 < w, eq0 = (d0 == w);
                    bool lt1 = d1 < w, eq1 = (d1 == w);
                    if (lt0 | (eq0 & (ties > 0))) {
                        g_idx[base + cnt2] = t0 + 2 * p;
                        cnt2++;
                        ties -= eq0 ? 1 : 0;
                    }
                    if (lt1 | (eq1 & (ties > 0))) {
                        g_idx[base + cnt2] = t0 + 2 * p + 1;
                        cnt2++;
                        ties -= eq1 ? 1 : 0;
                    }
                }
            }
        }
    }
}

// ---------------------------------------------------------------------------
// Kernel 2: warp per (b,i). Lane = channel pair. Coalesced 256B row gathers.
// Produces per-channel max/min of offsets + block partial of sum(offset^2).
// ---------------------------------------------------------------------------
__global__ void __launch_bounds__(256) gather_kernel(const float* __restrict__ feats) {
    const int gw   = (blockIdx.x << 3) + (threadIdx.x >> 5);   // b*NN + i
    const int lane = threadIdx.x & 31;
    const int b = gw >> 12;
    const int i = gw & (NN - 1);
    const float* fb = feats + ((size_t)b << 18);               // b*NN*CC

    const float2 ctr = *(const float2*)(fb + i * CC + lane * 2);
    const int myid = g_idx[gw * KNNK + lane];

    float mx0 = F_NINF, mx1 = F_NINF;
    float mn0 = F_INF,  mn1 = F_INF;
    float ss = 0.f;

#pragma unroll
    for (int k = 0; k < KNNK; k++) {
        int j = __shfl_sync(FULL, myid, k);
        float2 f = *(const float2*)(fb + j * CC + lane * 2);
        float o0 = f.x - ctr.x, o1 = f.y - ctr.y;
        mx0 = fmaxf(mx0, o0); mn0 = fminf(mn0, o0);
        mx1 = fmaxf(mx1, o1); mn1 = fminf(mn1, o1);
        ss = fmaf(o0, o0, ss);
        ss = fmaf(o1, o1, ss);
    }

    const int ob = gw * CC + lane * 2;
    *(float2*)(g_mx + ob) = make_float2(mx0, mx1);
    *(float2*)(g_mn + ob) = make_float2(mn0, mn1);

#pragma unroll
    for (int off = 16; off; off >>= 1)
        ss += __shfl_xor_sync(FULL, ss, off);

    __shared__ float bs[8];
    if (lane == 0) bs[threadIdx.x >> 5] = ss;
    __syncthreads();
    if (threadIdx.x == 0) {
        g_part[blockIdx.x] = bs[0] + bs[1] + bs[2] + bs[3] +
                             bs[4] + bs[5] + bs[6] + bs[7];
    }
}

// ---------------------------------------------------------------------------
// Kernel 3: reduce partials -> g_inv = 1/(sigma + eps)
// ---------------------------------------------------------------------------
__global__ void reduce_kernel() {
    __shared__ float sm[256];
    float s = 0.f;
    for (int t = threadIdx.x; t < BB * NN / 8; t += 256) s += g_part[t];
    sm[threadIdx.x] = s;
    __syncthreads();
#pragma unroll
    for (int o = 128; o; o >>= 1) {
        if (threadIdx.x < o) sm[threadIdx.x] += sm[threadIdx.x + o];
        __syncthreads();
    }
    if (threadIdx.x == 0) {
        float sigma = sm[0] / (float)((long long)BB * NN * KNNK * CC);
        g_inv = 1.f / (sigma + 1e-5f);
    }
}

// ---------------------------------------------------------------------------
// Kernel 4: pooled = select(alpha>=0, max, min) * inv * alpha + beta
// (max over k commutes with the positive/negative scale)
// ---------------------------------------------------------------------------
__global__ void __launch_bounds__(256) final_kernel(const float* __restrict__ alpha,
                                                    const float* __restrict__ beta,
                                                    float* __restrict__ out) {
    const int idx = blockIdx.x * 256 + threadIdx.x;   // float2 index, 2M total
    const float inv = g_inv;
    const int c2 = idx & (CC / 2 - 1);
    const float a0 = alpha[c2 * 2], a1 = alpha[c2 * 2 + 1];
    const float b0 = beta[c2 * 2],  b1 = beta[c2 * 2 + 1];
    const float2 mx = ((const float2*)g_mx)[idx];
    const float2 mn = ((const float2*)g_mn)[idx];
    float v0 = (a0 >= 0.f) ? mx.x : mn.x;
    float v1 = (a1 >= 0.f) ? mx.y : mn.y;
    float2 r;
    r.x = fmaf(v0 * inv, a0, b0);
    r.y = fmaf(v1 * inv, a1, b1);
    ((float2*)out)[idx] = r;
}

extern "C" void kernel_launch(void* const* d_in, const int* in_sizes, int n_in,
                              void* d_out, int out_size) {
    const float* xyz   = (const float*)d_in[0];
    const float* feats = (const float*)d_in[1];
    const float* alpha = (const float*)d_in[2];
    const float* beta  = (const float*)d_in[3];
    float* out = (float*)d_out;
    (void)in_sizes; (void)n_in; (void)out_size;

    knn_kernel<<<BB * NN / QB, QB>>>(xyz);
    gather_kernel<<<BB * NN / 8, 256>>>(feats);
    reduce_kernel<<<1, 256>>>();
    final_kernel<<<BB * NN * CC / 512, 256>>>(alpha, beta, out);
}

// round 6
// speedup vs baseline: 1.1215x; 1.0148x over previous
#include <cuda_runtime.h>

#define BB   16
#define NN   4096
#define CC   64
#define KNNK 32
#define TILE 2048
#define NPAIR (TILE / 2)
#define QB   128
#define CAP  320

#define F_INF  __int_as_float(0x7f800000)
#define F_NINF __int_as_float(0xff800000)
#define FULL   0xFFFFFFFFu

typedef unsigned long long ull;

// Scratch (static device globals — allowed; no runtime allocation).
__device__ int   g_idx[BB * NN * KNNK];      // 8 MB
__device__ float g_mx[BB * NN * CC];         // 16 MB
__device__ float g_mn[BB * NN * CC];         // 16 MB
__device__ float g_part[BB * NN / 8];        // 8192 block partials
__device__ float g_inv;

// ---- Blackwell packed f32x2 FMA (PTX-only; min/max.f32x2 do NOT exist) ----
__device__ __forceinline__ ull fma2(ull a, ull b, ull c) {
    ull d; asm("fma.rn.f32x2 %0, %1, %2, %3;" : "=l"(d) : "l"(a), "l"(b), "l"(c));
    return d;
}
__device__ __forceinline__ ull pk2(float lo, float hi) {
    ull r; asm("mov.b64 %0, {%1, %2};" : "=l"(r) : "f"(lo), "f"(hi));
    return r;
}
__device__ __forceinline__ void up2(ull v, float& lo, float& hi) {
    asm("mov.b64 {%0, %1}, %2;" : "=f"(lo), "=f"(hi) : "l"(v));
}

// Branchless insert of c into ascending sorted 32-reg array (drops old max).
__device__ __forceinline__ void insert32(float (&sv)[KNNK], float c) {
#pragma unroll
    for (int u = 0; u < KNNK; u++) {
        float lo = fminf(sv[u], c);
        c = fmaxf(sv[u], c);
        sv[u] = lo;
    }
}

// ---------------------------------------------------------------------------
// Kernel 1: exact 32-NN. Pre-packed pair tiles (zero pack cost in sweep),
// bitonic warm-up from the first 32 candidates (kills the flush storm),
// record+replay index recovery, block-uniform exact-rescan fallback.
// ---------------------------------------------------------------------------
__global__ void __launch_bounds__(QB) knn_kernel(const float* __restrict__ xyz) {
    // pair tiles: s_a[p]={x01,y01}, s_b[p]={z01,n01} for candidates 2p,2p+1
    __shared__ ulonglong2 s_a[NPAIR], s_b[NPAIR];    // 32 KB
    __shared__ int s_of;

    const int b = blockIdx.x >> 5;                   // 32 blocks per batch
    const int i = ((blockIdx.x & 31) << 7) + threadIdx.x;
    const float* xb = xyz + (size_t)b * (3 * NN);

    if (threadIdx.x == 0) s_of = 0;

    const float xi = xb[i], yi = xb[NN + i], zi = xb[2 * NN + i];
    const ull AX = pk2(-2.f * xi, -2.f * xi);
    const ull AY = pk2(-2.f * yi, -2.f * yi);
    const ull AZ = pk2(-2.f * zi, -2.f * zi);

    float2 rec[CAP];                                 // local mem (d, idx-bits)
    int rc = 0;
    bool ofl = false;

    float sv[KNNK];
    float worst;
    float b0 = F_INF, b1 = F_INF, b2 = F_INF, b3 = F_INF;
    int cnt = 0;

    // ---------------- Phase 1: values + accepted-candidate record ---------
    for (int t0 = 0; t0 < NN; t0 += TILE) {
        __syncthreads();
        for (int p = threadIdx.x; p < NPAIR; p += QB) {
            float2 X = *(const float2*)(xb + t0 + 2 * p);
            float2 Y = *(const float2*)(xb + NN + t0 + 2 * p);
            float2 Z = *(const float2*)(xb + 2 * NN + t0 + 2 * p);
            float n0 = fmaf(X.x, X.x, fmaf(Y.x, Y.x, Z.x * Z.x));
            float n1 = fmaf(X.y, X.y, fmaf(Y.y, Y.y, Z.y * Z.y));
            s_a[p] = make_ulonglong2(pk2(X.x, X.y), pk2(Y.x, Y.y));
            s_b[p] = make_ulonglong2(pk2(Z.x, Z.y), pk2(n0, n1));
        }
        __syncthreads();

        int pstart = 0;
        if (t0 == 0) {
            // ---- warm-up: first 32 candidates seed sv via bitonic sort ---
            pstart = KNNK / 2;                       // pairs 0..15 consumed
#pragma unroll
            for (int p = 0; p < KNNK / 2; p++) {
                ulonglong2 A = s_a[p];
                ulonglong2 B = s_b[p];
                ull d2 = fma2(AX, A.x, fma2(AY, A.y, fma2(AZ, B.x, B.y)));
                float d0, d1; up2(d2, d0, d1);
                sv[2 * p] = d0;
                sv[2 * p + 1] = d1;
                rec[rc++] = make_float2(d0, __int_as_float(2 * p));
                rec[rc++] = make_float2(d1, __int_as_float(2 * p + 1));
            }
            // bitonic sort sv ascending (compile-time network)
#pragma unroll
            for (int k = 2; k <= KNNK; k <<= 1) {
#pragma unroll
                for (int j = k >> 1; j > 0; j >>= 1) {
#pragma unroll
                    for (int u = 0; u < KNNK; u++) {
                        int l = u ^ j;
                        if (l > u) {
                            bool up = ((u & k) == 0);
                            float lo = fminf(sv[u], sv[l]);
                            float hi = fmaxf(sv[u], sv[l]);
                            sv[u] = up ? lo : hi;
                            sv[l] = up ? hi : lo;
                        }
                    }
                }
            }
            worst = sv[KNNK - 1];
        }

#pragma unroll 4
        for (int p = pstart; p < NPAIR; p++) {
            ulonglong2 A = s_a[p];
            ulonglong2 B = s_b[p];
            // d_rel = ||xj||^2 - 2 xi.xj  (ranking-equivalent to reference pd)
            ull d2 = fma2(AX, A.x, fma2(AY, A.y, fma2(AZ, B.x, B.y)));
            float d0, d1; up2(d2, d0, d1);
            bool p0 = d0 < worst;
            bool p1 = d1 < worst;
            if (__any_sync(FULL, p0 | p1)) {
                if (p0) {
                    b3 = b2; b2 = b1; b1 = b0; b0 = d0; cnt++;
                    if (rc < CAP) rec[rc++] = make_float2(d0, __int_as_float(t0 + 2 * p));
                    else ofl = true;
                }
                if (p1) {
                    b3 = b2; b2 = b1; b1 = b0; b0 = d1; cnt++;
                    if (rc < CAP) rec[rc++] = make_float2(d1, __int_as_float(t0 + 2 * p + 1));
                    else ofl = true;
                }
                if (__any_sync(FULL, cnt >= 3)) {
                    insert32(sv, b0); insert32(sv, b1);
                    insert32(sv, b2); insert32(sv, b3);
                    b0 = b1 = b2 = b3 = F_INF; cnt = 0;
                    worst = sv[KNNK - 1];
                }
            }
        }
    }
    // final flush (sentinels are harmless)
    insert32(sv, b0); insert32(sv, b1); insert32(sv, b2); insert32(sv, b3);

    const float w = sv[KNNK - 1];                    // exact 32nd smallest
    int ties = 1;                                    // emissions allowed at ==w
#pragma unroll
    for (int u = 0; u < KNNK - 1; u++) ties += (sv[u] == w);

    if (ofl) atomicOr(&s_of, 1);
    __syncthreads();
    const bool any_of = (s_of != 0);

    // ---------------- Phase 2a: replay recorded list (fast path) ----------
    const int base = (b * NN + i) * KNNK;
    if (!ofl) {
        int cnt2 = 0;
        for (int t = 0; t < rc; t++) {
            float2 r = rec[t];
            float d = r.x;
            bool lt = d < w;
            bool eq = (d == w);
            if (lt | (eq & (ties > 0))) {
                g_idx[base + cnt2] = __float_as_int(r.y);
                cnt2++;
                ties -= eq ? 1 : 0;
            }
        }
    }

    // ---------------- Phase 2b: exact rescan fallback (block-uniform) -----
    if (any_of) {
        int cnt2 = 0;
        for (int t0 = 0; t0 < NN; t0 += TILE) {
            __syncthreads();
            for (int p = threadIdx.x; p < NPAIR; p += QB) {
                float2 X = *(const float2*)(xb + t0 + 2 * p);
                float2 Y = *(const float2*)(xb + NN + t0 + 2 * p);
                float2 Z = *(const float2*)(xb + 2 * NN + t0 + 2 * p);
                float n0 = fmaf(X.x, X.x, fmaf(Y.x, Y.x, Z.x * Z.x));
                float n1 = fmaf(X.y, X.y, fmaf(Y.y, Y.y, Z.y * Z.y));
                s_a[p] = make_ulonglong2(pk2(X.x, X.y), pk2(Y.x, Y.y));
                s_b[p] = make_ulonglong2(pk2(Z.x, Z.y), pk2(n0, n1));
            }
            __syncthreads();

            if (ofl) {
                for (int p = 0; p < NPAIR; p++) {
                    ulonglong2 A = s_a[p];
                    ulonglong2 B = s_b[p];
                    ull d2 = fma2(AX, A.x, fma2(AY, A.y, fma2(AZ, B.x, B.y)));
                    float d0, d1; up2(d2, d0, d1);
                    bool lt0 = d0 < w, eq0 = (d0 == w);
                    bool lt1 = d1 < w, eq1 = (d1 == w);
                    if (lt0 | (eq0 & (ties > 0))) {
                        g_idx[base + cnt2] = t0 + 2 * p;
                        cnt2++;
                        ties -= eq0 ? 1 : 0;
                    }
                    if (lt1 | (eq1 & (ties > 0))) {
                        g_idx[base + cnt2] = t0 + 2 * p + 1;
                        cnt2++;
                        ties -= eq1 ? 1 : 0;
                    }
                }
            }
        }
    }
}

// ---------------------------------------------------------------------------
// Kernel 2: warp per (b,i). Lane = channel pair. Coalesced 256B row gathers.
// Produces per-channel max/min of offsets + block partial of sum(offset^2).
// ---------------------------------------------------------------------------
__global__ void __launch_bounds__(256) gather_kernel(const float* __restrict__ feats) {
    const int gw   = (blockIdx.x << 3) + (threadIdx.x >> 5);   // b*NN + i
    const int lane = threadIdx.x & 31;
    const int b = gw >> 12;
    const int i = gw & (NN - 1);
    const float* fb = feats + ((size_t)b << 18);               // b*NN*CC

    const float2 ctr = *(const float2*)(fb + i * CC + lane * 2);
    const int myid = g_idx[gw * KNNK + lane];

    float mx0 = F_NINF, mx1 = F_NINF;
    float mn0 = F_INF,  mn1 = F_INF;
    float ss = 0.f;

#pragma unroll
    for (int k = 0; k < KNNK; k++) {
        int j = __shfl_sync(FULL, myid, k);
        float2 f = *(const float2*)(fb + j * CC + lane * 2);
        float o0 = f.x - ctr.x, o1 = f.y - ctr.y;
        mx0 = fmaxf(mx0, o0); mn0 = fminf(mn0, o0);
        mx1 = fmaxf(mx1, o1); mn1 = fminf(mn1, o1);
        ss = fmaf(o0, o0, ss);
        ss = fmaf(o1, o1, ss);
    }

    const int ob = gw * CC + lane * 2;
    *(float2*)(g_mx + ob) = make_float2(mx0, mx1);
    *(float2*)(g_mn + ob) = make_float2(mn0, mn1);

#pragma unroll
    for (int off = 16; off; off >>= 1)
        ss += __shfl_xor_sync(FULL, ss, off);

    __shared__ float bs[8];
    if (lane == 0) bs[threadIdx.x >> 5] = ss;
    __syncthreads();
    if (threadIdx.x == 0) {
        g_part[blockIdx.x] = bs[0] + bs[1] + bs[2] + bs[3] +
                             bs[4] + bs[5] + bs[6] + bs[7];
    }
}

// ---------------------------------------------------------------------------
// Kernel 3: reduce partials -> g_inv = 1/(sigma + eps)
// ---------------------------------------------------------------------------
__global__ void reduce_kernel() {
    __shared__ float sm[256];
    float s = 0.f;
    for (int t = threadIdx.x; t < BB * NN / 8; t += 256) s += g_part[t];
    sm[threadIdx.x] = s;
    __syncthreads();
#pragma unroll
    for (int o = 128; o; o >>= 1) {
        if (threadIdx.x < o) sm[threadIdx.x] += sm[threadIdx.x + o];
        __syncthreads();
    }
    if (threadIdx.x == 0) {
        float sigma = sm[0] / (float)((long long)BB * NN * KNNK * CC);
        g_inv = 1.f / (sigma + 1e-5f);
    }
}

// ---------------------------------------------------------------------------
// Kernel 4: pooled = select(alpha>=0, max, min) * inv * alpha + beta
// (max over k commutes with the positive/negative scale)
// ---------------------------------------------------------------------------
__global__ void __launch_bounds__(256) final_kernel(const float* __restrict__ alpha,
                                                    const float* __restrict__ beta,
                                                    float* __restrict__ out) {
    const int idx = blockIdx.x * 256 + threadIdx.x;   // float2 index, 2M total
    const float inv = g_inv;
    const int c2 = idx & (CC / 2 - 1);
    const float a0 = alpha[c2 * 2], a1 = alpha[c2 * 2 + 1];
    const float b0 = beta[c2 * 2],  b1 = beta[c2 * 2 + 1];
    const float2 mx = ((const float2*)g_mx)[idx];
    const float2 mn = ((const float2*)g_mn)[idx];
    float v0 = (a0 >= 0.f) ? mx.x : mn.x;
    float v1 = (a1 >= 0.f) ? mx.y : mn.y;
    float2 r;
    r.x = fmaf(v0 * inv, a0, b0);
    r.y = fmaf(v1 * inv, a1, b1);
    ((float2*)out)[idx] = r;
}

extern "C" void kernel_launch(void* const* d_in, const int* in_sizes, int n_in,
                              void* d_out, int out_size) {
    const float* xyz   = (const float*)d_in[0];
    const float* feats = (const float*)d_in[1];
    const float* alpha = (const float*)d_in[2];
    const float* beta  = (const float*)d_in[3];
    float* out = (float*)d_out;
    (void)in_sizes; (void)n_in; (void)out_size;

    knn_kernel<<<BB * NN / QB, QB>>>(xyz);
    gather_kernel<<<BB * NN / 8, 256>>>(feats);
    reduce_kernel<<<1, 256>>>();
    final_kernel<<<BB * NN * CC / 512, 256>>>(alpha, beta, out);
}